// round 13
// baseline (speedup 1.0000x reference)
#include <cuda_runtime.h>
#include <cuda_bf16.h>
#include <cstdint>
#include <math.h>

#define TAU 0.5f
#define B 16
#define H 96
#define W 96
#define NPIX (H * W)
#define NT 768            // 24 warps
#define NWRP (NT / 32)
#define NWORDS 288        // 96 rows x 3 words
#define PADW ((H + 4) * 5)
#define BIG 100000

// static device scratch (no allocation)
__device__ float g_sum = 0.0f;
__device__ int g_done = 0;

// exact search over padded target bitmask for one pixel (rare / far path)
__device__ __noinline__ int full_search(const uint32_t* mtp, int x, int y)
{
    int best = BIG;
    for (int yy = 0; yy < H; yy++) {
        int dy2 = (yy - y) * (yy - y);
        if (dy2 >= best) continue;
        #pragma unroll
        for (int w = 0; w < 3; w++) {
            uint32_t m = mtp[(yy + 2) * 5 + 1 + w];
            while (m) {
                int bp = __ffs(m) - 1; m &= m - 1;
                int dx = w * 32 + bp - x;
                best = min(best, dy2 + dx * dx);
            }
        }
    }
    return best;
}

// directed max-min d2 for one 32-px word vs dilations of target mask
__device__ __forceinline__ int dilate_eval(const uint32_t* mtp, uint32_t q,
                                           int y, int wc)
{
    uint32_t C[5], h1[5], h2[5];
    #pragma unroll
    for (int j = 0; j < 5; j++) {
        uint32_t l = mtp[(y + j) * 5 + wc];
        uint32_t c = mtp[(y + j) * 5 + wc + 1];
        uint32_t r = mtp[(y + j) * 5 + wc + 2];
        C[j]  = c;
        h1[j] = __funnelshift_l(l, c, 1) | __funnelshift_r(c, r, 1);
        h2[j] = __funnelshift_l(l, c, 2) | __funnelshift_r(c, r, 2);
    }
    uint32_t D0 = C[2];
    uint32_t D1 = D0 | h1[2] | C[1] | C[3];
    uint32_t D2 = D1 | h1[1] | h1[3];
    uint32_t D4 = D2 | h2[2] | C[0] | C[4];
    uint32_t D5 = D4 | h2[1] | h2[3] | h1[0] | h1[4];
    uint32_t D8 = D5 | h2[0] | h2[4];

    int p = (q & ~D5) ? 8 : (q & ~D4) ? 5 : (q & ~D2) ? 4
          : (q & ~D1) ? 2 : (q & ~D0) ? 1 : 0;
    uint32_t fb = q & ~D8;               // d2 >= 9: exact fallback (~never)
    while (fb) {
        int bp = __ffs(fb) - 1; fb &= fb - 1;
        p = max(p, full_search(mtp, wc * 32 + bp, y));
    }
    return p;
}

__global__ void __launch_bounds__(NT, 1)
hd_all(const float* __restrict__ pred,
       const float* __restrict__ tgt,
       float* __restrict__ out)
{
    __shared__ uint32_t mP[PADW];        // padded pred mask
    __shared__ uint32_t mL[PADW];        // padded label mask
    __shared__ int sAB[NWRP], sBA[NWRP], sANY[NWRP];
    __shared__ int s_last, s_needs, s_diam;

    const int img  = blockIdx.x;
    const int tid  = threadIdx.x;
    const int lane = tid & 31;
    const int wrp  = tid >> 5;

    const float4* srcP = (const float4*)(pred + img * NPIX);
    const float4* srcL = (const float4*)(tgt  + img * NPIX);

    // ---- issue ALL loads first (latency overlaps pad-zeroing below) ----
    float4 vp[3], vl[3];
    #pragma unroll
    for (int k = 0; k < 3; k++) {
        vp[k] = srcP[tid + k * NT];
        vl[k] = srcL[tid + k * NT];
    }

    // zero ONLY pad words (disjoint from interior writes -> no barrier needed)
    #pragma unroll
    for (int i = tid; i < 2 * PADW; i += NT) {
        int ii = (i < PADW) ? i : i - PADW;
        int r = ii / 5, c = ii - r * 5;
        if (r < 2 || r >= H + 2 || c == 0 || c == 4) {
            if (i < PADW) mP[ii] = 0u; else mL[ii] = 0u;
        }
    }

    // ---- phase A: assemble both masks (nibble -> shfl-or, 8-lane groups) ----
    #pragma unroll
    for (int k = 0; k < 3; k++) {
        int i4 = tid + k * NT;
        uint32_t np = (vp[k].x >= TAU ? 1u : 0u) | (vp[k].y >= TAU ? 2u : 0u)
                    | (vp[k].z >= TAU ? 4u : 0u) | (vp[k].w >= TAU ? 8u : 0u);
        uint32_t nl = (vl[k].x >= TAU ? 1u : 0u) | (vl[k].y >= TAU ? 2u : 0u)
                    | (vl[k].z >= TAU ? 4u : 0u) | (vl[k].w >= TAU ? 8u : 0u);
        int shft = (i4 & 7) * 4;
        uint32_t wp = np << shft;
        uint32_t wl = nl << shft;
        wp |= __shfl_xor_sync(0xFFFFFFFFu, wp, 1);
        wl |= __shfl_xor_sync(0xFFFFFFFFu, wl, 1);
        wp |= __shfl_xor_sync(0xFFFFFFFFu, wp, 2);
        wl |= __shfl_xor_sync(0xFFFFFFFFu, wl, 2);
        wp |= __shfl_xor_sync(0xFFFFFFFFu, wp, 4);
        wl |= __shfl_xor_sync(0xFFFFFFFFu, wl, 4);
        if ((lane & 7) == 0) {
            int w = i4 >> 3;              // word index = y*3 + xw
            int y = w / 3, xw = w - y * 3;
            mP[(y + 2) * 5 + 1 + xw] = wp;
            mL[(y + 2) * 5 + 1 + xw] = wl;
        }
    }
    __syncthreads();                      // the ONLY pre-compute barrier

    // ---- phase B: directions split across threads (one dilate per thread) ----
    int pmaxAB = 0, pmaxBA = 0, any = 0;  // any: bit0=predAny, bit1=labelAny
    if (tid < NWORDS) {
        const int y  = tid / 3;
        const int wc = tid - y * 3;
        uint32_t qP = mP[(y + 2) * 5 + 1 + wc];
        any = qP ? 1 : 0;
        pmaxAB = dilate_eval(mL, qP, y, wc);          // pred -> label
    } else if (tid < 2 * NWORDS) {
        const int t  = tid - NWORDS;
        const int y  = t / 3;
        const int wc = t - y * 3;
        uint32_t qL = mL[(y + 2) * 5 + 1 + wc];
        any = qL ? 2 : 0;
        pmaxBA = dilate_eval(mP, qL, y, wc);          // label -> pred
    }

    // ---- block reduction (REDUX single-instruction warp reduce) ----
    pmaxAB = __reduce_max_sync(0xFFFFFFFFu, pmaxAB);
    pmaxBA = __reduce_max_sync(0xFFFFFFFFu, pmaxBA);
    any    = __reduce_or_sync (0xFFFFFFFFu, any);
    if (lane == 0) { sAB[wrp] = pmaxAB; sBA[wrp] = pmaxBA; sANY[wrp] = any; }
    __syncthreads();

    float myhd = 0.0f;                    // meaningful on tid 0 only
    if (tid < 32) {
        int a = (tid < NWRP) ? sAB[tid] : 0;
        int b = (tid < NWRP) ? sBA[tid] : 0;
        int n = (tid < NWRP) ? sANY[tid] : 0;
        a = __reduce_max_sync(0xFFFFFFFFu, a);
        b = __reduce_max_sync(0xFFFFFFFFu, b);
        n = __reduce_or_sync (0xFFFFFFFFu, n);
        if (tid == 0) {
            int aP = n & 1, aL = (n >> 1) & 1;
            if (aP && aL)        { myhd = sqrtf((float)max(a, b)); s_needs = 0; }
            else if (!aP && !aL) { myhd = 0.0f; s_needs = 0; }
            else                 { s_needs = aP ? 1 : 2; }  // diameter fallback
        }
    }
    __syncthreads();

    // ---- in-block empty-set fallback: diameter via bitmask (never runs here) ----
    if (s_needs) {
        const uint32_t* m = (s_needs == 1) ? mP : mL;
        if (tid == 0) s_diam = 0;
        __syncthreads();
        int best = 0;
        if (tid < NWORDS) {
            int y = tid / 3, wc = tid - y * 3;
            uint32_t bits = m[(y + 2) * 5 + 1 + wc];
            while (bits) {
                int bp = __ffs(bits) - 1; bits &= bits - 1;
                int x = wc * 32 + bp;
                for (int yy = 0; yy < H; yy++) {
                    int dy2 = (yy - y) * (yy - y);
                    #pragma unroll
                    for (int w = 0; w < 3; w++) {
                        uint32_t mm = m[(yy + 2) * 5 + 1 + w];
                        while (mm) {
                            int bq = __ffs(mm) - 1; mm &= mm - 1;
                            int dx = w * 32 + bq - x;
                            best = max(best, dy2 + dx * dx);
                        }
                    }
                }
            }
        }
        atomicMax(&s_diam, best);
        __syncthreads();
        if (tid == 0) myhd = sqrtf((float)s_diam);
    }

    // ---- tail: accumulate mean; last block writes the scalar ----
    if (tid == 0) {
        atomicAdd(&g_sum, myhd);
        __threadfence();
        int old = atomicAdd(&g_done, 1);
        s_last = (old == B - 1);
    }
    __syncthreads();
    if (!s_last) return;
    if (tid == 0) {
        __threadfence();
        float s = *(volatile float*)&g_sum;
        out[0] = s * (1.0f / B);
        g_sum = 0.0f;                     // reset for next graph replay
        g_done = 0;
    }
}

// ---------------------------------------------------------------------------
extern "C" void kernel_launch(void* const* d_in, const int* in_sizes, int n_in,
                              void* d_out, int out_size)
{
    const float* pred = (const float*)d_in[0];
    const float* tgt  = (const float*)d_in[1];
    float* out = (float*)d_out;

    hd_all<<<B, NT>>>(pred, tgt, out);
}

// round 14
// speedup vs baseline: 1.3478x; 1.3478x over previous
#include <cuda_runtime.h>
#include <cuda_bf16.h>
#include <cstdint>
#include <math.h>

#define TAU 0.5f
#define B 16
#define H 96
#define W 96
#define NPIX (H * W)
#define NT 768            // 24 warps
#define NWRP (NT / 32)
#define NWORDS 288        // 96 rows x 3 words
#define PADW ((H + 4) * 5)
#define BIG 100000
#define FPSCALE 1048576.0f       // 2^20 fixed-point for the packed mean
#define CNT_SHIFT 40             // arrival counter lives at bit 40

// static device scratch (no allocation)
__device__ unsigned long long g_pack = 0ull;   // [63:40] count, [39:0] fixed-point sum

// exact search over padded target bitmask for one pixel (rare / far path)
__device__ __noinline__ int full_search(const uint32_t* mtp, int x, int y)
{
    int best = BIG;
    for (int yy = 0; yy < H; yy++) {
        int dy2 = (yy - y) * (yy - y);
        if (dy2 >= best) continue;
        #pragma unroll
        for (int w = 0; w < 3; w++) {
            uint32_t m = mtp[(yy + 2) * 5 + 1 + w];
            while (m) {
                int bp = __ffs(m) - 1; m &= m - 1;
                int dx = w * 32 + bp - x;
                best = min(best, dy2 + dx * dx);
            }
        }
    }
    return best;
}

// directed max-min d2 for one 32-px word vs dilations of target mask
__device__ __forceinline__ int dilate_eval(const uint32_t* mtp, uint32_t q,
                                           int y, int wc)
{
    uint32_t C[5], h1[5], h2[5];
    #pragma unroll
    for (int j = 0; j < 5; j++) {
        uint32_t l = mtp[(y + j) * 5 + wc];
        uint32_t c = mtp[(y + j) * 5 + wc + 1];
        uint32_t r = mtp[(y + j) * 5 + wc + 2];
        C[j]  = c;
        h1[j] = __funnelshift_l(l, c, 1) | __funnelshift_r(c, r, 1);
        h2[j] = __funnelshift_l(l, c, 2) | __funnelshift_r(c, r, 2);
    }
    uint32_t D0 = C[2];
    uint32_t D1 = D0 | h1[2] | C[1] | C[3];
    uint32_t D2 = D1 | h1[1] | h1[3];
    uint32_t D4 = D2 | h2[2] | C[0] | C[4];
    uint32_t D5 = D4 | h2[1] | h2[3] | h1[0] | h1[4];
    uint32_t D8 = D5 | h2[0] | h2[4];

    int p = (q & ~D5) ? 8 : (q & ~D4) ? 5 : (q & ~D2) ? 4
          : (q & ~D1) ? 2 : (q & ~D0) ? 1 : 0;
    uint32_t fb = q & ~D8;               // d2 >= 9: exact fallback (~never)
    while (fb) {
        int bp = __ffs(fb) - 1; fb &= fb - 1;
        p = max(p, full_search(mtp, wc * 32 + bp, y));
    }
    return p;
}

__global__ void __launch_bounds__(NT, 1)
hd_all(const float* __restrict__ pred,
       const float* __restrict__ tgt,
       float* __restrict__ out)
{
    __shared__ uint32_t mP[PADW];        // padded pred mask
    __shared__ uint32_t mL[PADW];        // padded label mask
    __shared__ int sAB[NWRP], sBA[NWRP], sANY[NWRP];
    __shared__ int s_diam;

    const int img  = blockIdx.x;
    const int tid  = threadIdx.x;
    const int lane = tid & 31;
    const int wrp  = tid >> 5;

    const float4* srcP = (const float4*)(pred + img * NPIX);
    const float4* srcL = (const float4*)(tgt  + img * NPIX);

    // ---- issue ALL loads first (latency overlaps pad-zeroing below) ----
    float4 vp[3], vl[3];
    #pragma unroll
    for (int k = 0; k < 3; k++) {
        vp[k] = srcP[tid + k * NT];
        vl[k] = srcL[tid + k * NT];
    }

    // zero ONLY pad words (disjoint from interior writes -> no barrier needed)
    #pragma unroll
    for (int i = tid; i < 2 * PADW; i += NT) {
        int ii = (i < PADW) ? i : i - PADW;
        int r = ii / 5, c = ii - r * 5;
        if (r < 2 || r >= H + 2 || c == 0 || c == 4) {
            if (i < PADW) mP[ii] = 0u; else mL[ii] = 0u;
        }
    }

    // ---- phase A: assemble both masks (nibble -> shfl-or, 8-lane groups) ----
    #pragma unroll
    for (int k = 0; k < 3; k++) {
        int i4 = tid + k * NT;
        uint32_t np = (vp[k].x >= TAU ? 1u : 0u) | (vp[k].y >= TAU ? 2u : 0u)
                    | (vp[k].z >= TAU ? 4u : 0u) | (vp[k].w >= TAU ? 8u : 0u);
        uint32_t nl = (vl[k].x >= TAU ? 1u : 0u) | (vl[k].y >= TAU ? 2u : 0u)
                    | (vl[k].z >= TAU ? 4u : 0u) | (vl[k].w >= TAU ? 8u : 0u);
        int shft = (i4 & 7) * 4;
        uint32_t wp = np << shft;
        uint32_t wl = nl << shft;
        wp |= __shfl_xor_sync(0xFFFFFFFFu, wp, 1);
        wl |= __shfl_xor_sync(0xFFFFFFFFu, wl, 1);
        wp |= __shfl_xor_sync(0xFFFFFFFFu, wp, 2);
        wl |= __shfl_xor_sync(0xFFFFFFFFu, wl, 2);
        wp |= __shfl_xor_sync(0xFFFFFFFFu, wp, 4);
        wl |= __shfl_xor_sync(0xFFFFFFFFu, wl, 4);
        if ((lane & 7) == 0) {
            int w = i4 >> 3;              // word index = y*3 + xw
            int y = w / 3, xw = w - y * 3;
            mP[(y + 2) * 5 + 1 + xw] = wp;
            mL[(y + 2) * 5 + 1 + xw] = wl;
        }
    }
    __syncthreads();                      // barrier #1

    // ---- phase B: directions split across threads (one dilate per thread) ----
    int pmaxAB = 0, pmaxBA = 0, any = 0;  // any: bit0=predAny, bit1=labelAny
    if (tid < NWORDS) {
        const int y  = tid / 3;
        const int wc = tid - y * 3;
        uint32_t qP = mP[(y + 2) * 5 + 1 + wc];
        any = qP ? 1 : 0;
        pmaxAB = dilate_eval(mL, qP, y, wc);          // pred -> label
    } else if (tid < 2 * NWORDS) {
        const int t  = tid - NWORDS;
        const int y  = t / 3;
        const int wc = t - y * 3;
        uint32_t qL = mL[(y + 2) * 5 + 1 + wc];
        any = qL ? 2 : 0;
        pmaxBA = dilate_eval(mP, qL, y, wc);          // label -> pred
    }

    // ---- per-warp REDUX, publish, ONE barrier, then all-warp final reduce ----
    pmaxAB = __reduce_max_sync(0xFFFFFFFFu, pmaxAB);
    pmaxBA = __reduce_max_sync(0xFFFFFFFFu, pmaxBA);
    any    = __reduce_or_sync (0xFFFFFFFFu, any);
    if (lane == 0) { sAB[wrp] = pmaxAB; sBA[wrp] = pmaxBA; sANY[wrp] = any; }
    __syncthreads();                      // barrier #2 (last in the hot path)

    // every warp redundantly reduces the 24 partials -> uniform a/b/n, no barrier
    int a = 0, b = 0, n = 0;
    if (lane < NWRP) { a = sAB[lane]; b = sBA[lane]; n = sANY[lane]; }
    a = __reduce_max_sync(0xFFFFFFFFu, a);
    b = __reduce_max_sync(0xFFFFFFFFu, b);
    n = __reduce_or_sync (0xFFFFFFFFu, n);

    const int aP = n & 1, aL = (n >> 1) & 1;
    const int needs = (aP && aL) ? 0 : (aP ? 1 : (aL ? 2 : 0));   // uniform block-wide
    float myhd = (aP && aL) ? sqrtf((float)max(a, b)) : 0.0f;

    // ---- in-block empty-set fallback: diameter via bitmask (never runs here) ----
    if (needs) {                          // uniform branch; safe to sync inside
        const uint32_t* m = (needs == 1) ? mP : mL;
        if (tid == 0) s_diam = 0;
        __syncthreads();
        int best = 0;
        if (tid < NWORDS) {
            int y = tid / 3, wc = tid - y * 3;
            uint32_t bits = m[(y + 2) * 5 + 1 + wc];
            while (bits) {
                int bp = __ffs(bits) - 1; bits &= bits - 1;
                int x = wc * 32 + bp;
                for (int yy = 0; yy < H; yy++) {
                    int dy2 = (yy - y) * (yy - y);
                    #pragma unroll
                    for (int w = 0; w < 3; w++) {
                        uint32_t mm = m[(yy + 2) * 5 + 1 + w];
                        while (mm) {
                            int bq = __ffs(mm) - 1; mm &= mm - 1;
                            int dx = w * 32 + bq - x;
                            best = max(best, dy2 + dx * dx);
                        }
                    }
                }
            }
        }
        atomicMax(&s_diam, best);
        __syncthreads();
        myhd = sqrtf((float)s_diam);
    }

    // ---- tail: ONE packed atomic; its return value is the synchronization ----
    if (tid == 0) {
        // fixed-point: deterministic integer accumulation (order-independent)
        unsigned long long add =
            (unsigned long long)__float2ull_rn(myhd * FPSCALE)
            + (1ull << CNT_SHIFT);
        unsigned long long old = atomicAdd(&g_pack, add);
        if ((old >> CNT_SHIFT) == B - 1) {            // I am the last block
            unsigned long long total = (old + add) & ((1ull << CNT_SHIFT) - 1ull);
            out[0] = (float)total * (1.0f / (B * FPSCALE));
            g_pack = 0ull;                // reset for next graph replay
        }
    }
}

// ---------------------------------------------------------------------------
extern "C" void kernel_launch(void* const* d_in, const int* in_sizes, int n_in,
                              void* d_out, int out_size)
{
    const float* pred = (const float*)d_in[0];
    const float* tgt  = (const float*)d_in[1];
    float* out = (float*)d_out;

    hd_all<<<B, NT>>>(pred, tgt, out);
}